// round 17
// baseline (speedup 1.0000x reference)
#include <cuda_runtime.h>
#include <cuda_fp16.h>
#include <cstdint>
#include <cstddef>

// Problem constants
#define HOPS 3
#define VV   50000
#define DD   128
#define BB   16
#define LC   256
#define MC   8
#define LK   512
#define MK   8

// Attention tiling
#define TQ 64          // q rows per block (4 warps x 16-row strips)
#define TK 64          // kf rows per chunk
#define KS 2           // k-split factor
#define CHUNKS (LK / TK / KS)   // 4 chunks per block
#define KF_PITCH 136   // halves; 272B row stride (16B-odd -> conflict-free ldsm)
#define NBLK (4 * BB * HOPS * KS)   // 384 attn blocks
#define NTHR_TOT (NBLK * 128)       // 49152

// ---------------- device scratch ----------------
__device__ __half g_cf[(size_t)HOPS * BB * LC * DD];
__device__ __half g_kf[(size_t)HOPS * BB * LK * DD];
__device__ __half g_part[(size_t)HOPS * KS * LC * BB * DD]; // fp16 partial AV
__device__ float  g_psum[(size_t)HOPS * KS * LC * BB];      // partial row sums
__device__ unsigned g_done  = 0;   // arrival counter (reset by last arriver)
__device__ unsigned g_epoch = 0;   // monotonic epoch (graph-replay safe)

// ---------------- warp-MMA helpers (portable PTX) --------
__device__ __forceinline__ uint32_t smem_u32(const void* p) {
    uint32_t a;
    asm("{ .reg .u64 t; cvta.to.shared.u64 t, %1; cvt.u32.u64 %0, t; }"
        : "=r"(a) : "l"(p));
    return a;
}
__device__ __forceinline__ void ldsm_x4(uint32_t a[4], uint32_t addr) {
    asm volatile("ldmatrix.sync.aligned.m8n8.x4.shared.b16 {%0,%1,%2,%3}, [%4];"
                 : "=r"(a[0]), "=r"(a[1]), "=r"(a[2]), "=r"(a[3]) : "r"(addr));
}
__device__ __forceinline__ void ldsm_x4_t(uint32_t a[4], uint32_t addr) {
    asm volatile("ldmatrix.sync.aligned.m8n8.x4.trans.shared.b16 {%0,%1,%2,%3}, [%4];"
                 : "=r"(a[0]), "=r"(a[1]), "=r"(a[2]), "=r"(a[3]) : "r"(addr));
}
__device__ __forceinline__ void mma16816(float d[4], const uint32_t a[4],
                                         const uint32_t b0, const uint32_t b1) {
    asm volatile("mma.sync.aligned.m16n8k16.row.col.f32.f16.f16.f32 "
                 "{%0,%1,%2,%3}, {%4,%5,%6,%7}, {%8,%9}, {%0,%1,%2,%3};"
                 : "+f"(d[0]), "+f"(d[1]), "+f"(d[2]), "+f"(d[3])
                 : "r"(a[0]), "r"(a[1]), "r"(a[2]), "r"(a[3]),
                   "r"(b0), "r"(b1));
}
__device__ __forceinline__ void cp16(uint32_t dst, const void* src) {
    asm volatile("cp.async.cg.shared.global [%0], [%1], 16;"
                 :: "r"(dst), "l"(src) : "memory");
}
#define CP_COMMIT() asm volatile("cp.async.commit_group;" ::: "memory")
#define CP_WAIT0()  asm volatile("cp.async.wait_group 0;" ::: "memory")

__device__ __forceinline__ uint32_t h2u(float a, float b) {
    __half2 h = __floats2half2_rn(a, b);
    return *reinterpret_cast<uint32_t*>(&h);
}

// ---------------------------------------------------------------------------
// Kernel 1: embedding-bag -> plain fp16. 1 row/warp, 4 rows/block (best shape).
// ---------------------------------------------------------------------------
__global__ void embed_kernel(const int* __restrict__ conv,
                             const int* __restrict__ kb,
                             const float* __restrict__ Ctab,
                             const float* __restrict__ Ktab) {
    const int lane = threadIdx.x & 31;
    const int row  = blockIdx.x * 4 + (threadIdx.x >> 5);
    const int NC   = HOPS * BB * LC;

    const int* idx;
    const float* tab;
    __half* dst;
    if (row < NC) {
        const int hop = row / (BB * LC);
        const int rem = row - hop * (BB * LC);
        idx = conv + rem * MC;
        tab = Ctab + (size_t)hop * VV * DD;
        dst = g_cf + (size_t)row * DD;
    } else {
        const int r2  = row - NC;
        const int hop = r2 / (BB * LK);
        const int rem = r2 - hop * (BB * LK);
        idx = kb + rem * MK;
        tab = Ktab + (size_t)hop * VV * DD;
        dst = g_kf + (size_t)r2 * DD;
    }
    float4 s = make_float4(0.f, 0.f, 0.f, 0.f);
    #pragma unroll
    for (int m = 0; m < 8; m++) {
        const float4 v = ((const float4*)(tab + (size_t)idx[m] * DD))[lane];
        s.x += v.x; s.y += v.y; s.z += v.z; s.w += v.w;
    }
    ((__half2*)(dst + 4 * lane))[0] = __floats2half2_rn(s.x, s.y);
    ((__half2*)(dst + 4 * lane))[1] = __floats2half2_rn(s.z, s.w);
}

// ---------------------------------------------------------------------------
// Kernel 2: warp-MMA flash attention + fused device-wide reduce tail.
// grid = (LC/TQ, BB, HOPS*KS) = 384 blocks, 128 thr, 4 blocks/SM
// (384 <= 592 co-resident slots -> arrive+spin barrier is deadlock-free).
// After all blocks store partials, every block reduces a 1/384 slice of out.
// ---------------------------------------------------------------------------
extern __shared__ __half smem_h[];

__global__ __launch_bounds__(128, 4)
void attn_kernel(float* __restrict__ outp) {
    const int tid  = threadIdx.x;
    const int lane = tid & 31;
    const int w    = tid >> 5;
    const int g    = lane >> 2;
    const int t4   = lane & 3;
    const int lbase  = blockIdx.x * TQ;
    const int b      = blockIdx.y;
    const int hop    = blockIdx.z >> 1;
    const int ksplit = blockIdx.z & 1;
    const int pair   = hop * BB + b;

    const uint32_t sb = smem_u32(smem_h);
    const uint32_t BUFSZ = TK * KF_PITCH * 2;   // 17408 bytes per plane

    // ---- stage cf into plane 2 (plain stores), issue chunk0 cp.async ----
    {
        const uint4* sh = (const uint4*)(g_cf + ((size_t)pair * LC + lbase) * DD);
        __half* cfp = smem_h + 2 * TK * KF_PITCH;
        for (int i = tid; i < TQ * (DD / 8); i += 128) {
            const int r  = i >> 4;
            const int c8 = i & 15;
            *(uint4*)&cfp[r * KF_PITCH + c8 * 8] = sh[r * (DD / 8) + c8];
        }
        const int ch0 = ksplit * CHUNKS;
        const uint4* kh = (const uint4*)(g_kf + ((size_t)pair * LK + ch0 * TK) * DD);
        for (int i = tid; i < TK * (DD / 8); i += 128) {
            const int r  = i >> 4;
            const int c8 = i & 15;
            cp16(sb + (uint32_t)(r * KF_PITCH + c8 * 8) * 2u, kh + r * (DD / 8) + c8);
        }
        CP_COMMIT();
    }
    __syncthreads();                       // cf visible
    CP_WAIT0();
    __syncthreads();                       // chunk0 ready

    // A-fragment address components (reload from cf plane per use)
    const uint32_t cfpl = sb + 2 * BUFSZ;
    const int asub = lane >> 3;
    const uint32_t a_row_off =
        (uint32_t)(w * 16 + (lane & 7) + ((asub & 1) << 3)) * KF_PITCH;
    const uint32_t a_col0 = (uint32_t)((asub & 2) << 2);

    // x4 lane addressing components
    const int r8   = lane & 7;
    const int gq   = lane >> 3;
    const uint32_t sc_row_off = (uint32_t)(((gq >> 1) << 3) + r8);
    const uint32_t sc_col_off = (uint32_t)((gq & 1) << 3);
    const uint32_t av_row_off = (uint32_t)(((gq & 1) << 3) + r8);
    const uint32_t av_col_off = (uint32_t)((gq >> 1) << 3);

    float out[16][4];
    #pragma unroll
    for (int i = 0; i < 16; i++)
        #pragma unroll
        for (int q = 0; q < 4; q++) out[i][q] = 0.f;
    float sum_r = 0.f, sum_r8 = 0.f;

    for (int c = 0; c < CHUNKS; c++) {
        if (c < CHUNKS - 1) {
            const int chn = ksplit * CHUNKS + c + 1;
            const uint32_t db = sb + (uint32_t)((c + 1) & 1) * BUFSZ;
            const uint4* kh = (const uint4*)(g_kf + ((size_t)pair * LK + chn * TK) * DD);
            for (int i = tid; i < TK * (DD / 8); i += 128) {
                const int r  = i >> 4;
                const int c8 = i & 15;
                cp16(db + (uint32_t)(r * KF_PITCH + c8 * 8) * 2u, kh + r * (DD / 8) + c8);
            }
            CP_COMMIT();
        }

        const uint32_t kf_b = sb + (uint32_t)(c & 1) * BUFSZ;

        // ---- scores + exp; 4 independent acc chains (32 kf rows / pass) ----
        uint32_t pa[4][4];
        #pragma unroll
        for (int p = 0; p < 2; p++) {
            float acc[4][4];
            #pragma unroll
            for (int j = 0; j < 4; j++)
                #pragma unroll
                for (int q = 0; q < 4; q++) acc[j][q] = 0.f;
            const uint32_t rbA = (uint32_t)(p * 32) + sc_row_off;
            const uint32_t rbB = rbA + 16;
            #pragma unroll
            for (int ks = 0; ks < 8; ks++) {
                uint32_t aa[4], bA[4], bB[4];
                ldsm_x4(aa, cfpl + (a_row_off + (uint32_t)(16 * ks) + a_col0) * 2u);
                const uint32_t ko = (uint32_t)(16 * ks) + sc_col_off;
                ldsm_x4(bA, kf_b + (rbA * KF_PITCH + ko) * 2u);
                ldsm_x4(bB, kf_b + (rbB * KF_PITCH + ko) * 2u);
                mma16816(acc[0], aa, bA[0], bA[1]);
                mma16816(acc[1], aa, bA[2], bA[3]);
                mma16816(acc[2], aa, bB[0], bB[1]);
                mma16816(acc[3], aa, bB[2], bB[3]);
            }
            #pragma unroll
            for (int j = 0; j < 4; j++) {
                const int nb = 4 * p + j;
                const float e0 = __expf(acc[j][0]);
                const float e1 = __expf(acc[j][1]);
                const float e2 = __expf(acc[j][2]);
                const float e3 = __expf(acc[j][3]);
                sum_r  += e0 + e1;
                sum_r8 += e2 + e3;
                // D-layout == AV A-layout identity
                pa[nb >> 1][((nb & 1) << 1) + 0] = h2u(e0, e1);
                pa[nb >> 1][((nb & 1) << 1) + 1] = h2u(e2, e3);
            }
        }

        // ---- AV: A = P (regs), B = kf via x4 trans (two dn per load) ----
        #pragma unroll
        for (int dnp = 0; dnp < 8; dnp++) {
            const uint32_t cb = (uint32_t)(dnp * 16) + av_col_off;
            #pragma unroll
            for (int ks = 0; ks < 4; ks++) {
                uint32_t b_h[4];
                const uint32_t off =
                    (((uint32_t)(16 * ks) + av_row_off) * KF_PITCH + cb) * 2u;
                ldsm_x4_t(b_h, kf_b + off);
                mma16816(out[2 * dnp],     pa[ks], b_h[0], b_h[1]);
                mma16816(out[2 * dnp + 1], pa[ks], b_h[2], b_h[3]);
            }
        }

        if (c < CHUNKS - 1) {
            CP_WAIT0();
            __syncthreads();               // next chunk ready; buffer swap safe
        }
    }

    // ---- finalize: quad-reduce row sums, store fp16 partials + fp32 sums ----
    #pragma unroll
    for (int off = 1; off <= 2; off <<= 1) {
        sum_r  += __shfl_xor_sync(0xffffffffu, sum_r,  off);
        sum_r8 += __shfl_xor_sync(0xffffffffu, sum_r8, off);
    }
    const int z = blockIdx.z;
    const int l0 = lbase + w * 16 + g;
    __half* slab = g_part + (size_t)z * LC * BB * DD;
    __half* op0 = slab + ((size_t)l0 * BB + b) * DD;
    __half* op8 = slab + ((size_t)(l0 + 8) * BB + b) * DD;
    if (t4 == 0) {
        g_psum[(size_t)z * LC * BB + (size_t)l0 * BB + b]       = sum_r;
        g_psum[(size_t)z * LC * BB + (size_t)(l0 + 8) * BB + b] = sum_r8;
    }
    #pragma unroll
    for (int dn = 0; dn < 16; dn++) {
        const int col = dn * 8 + 2 * t4;
        *(__half2*)&op0[col] = __floats2half2_rn(out[dn][0], out[dn][1]);
        *(__half2*)&op8[col] = __floats2half2_rn(out[dn][2], out[dn][3]);
    }

    // ================= device-wide barrier (epoch-based, replay-safe) =====
    __syncthreads();                 // all warps' partial stores issued
    __threadfence();                 // release: partials visible device-wide
    if (tid == 0) {
        const unsigned my_e = ((volatile unsigned*)&g_epoch)[0];
        const unsigned old = atomicAdd(&g_done, 1u);
        if (old == NBLK - 1) {       // last arriver: reset counter, bump epoch
            g_done = 0;
            __threadfence();
            atomicAdd(&g_epoch, 1u);
        } else {
            while (((volatile unsigned*)&g_epoch)[0] == my_e) __nanosleep(64);
        }
    }
    __syncthreads();
    __threadfence();                 // acquire: see all blocks' partials

    // ================= fused reduce phase =================
    {
        const int bid = blockIdx.x + 4 * blockIdx.y + 64 * blockIdx.z;
        const int n4 = LC * BB * (DD / 4);                 // 131072
        const size_t N4 = (size_t)n4;
        for (int i = bid * 128 + tid; i < n4; i += NTHR_TOT) {
            const int rowIdx = i >> 5;                     // (l*BB+b)
            float4 r = make_float4(0.f, 0.f, 0.f, 0.f);
            #pragma unroll
            for (int h = 0; h < HOPS; h++) {
                const float s = g_psum[(size_t)(h * KS) * LC * BB + rowIdx] +
                                g_psum[(size_t)(h * KS + 1) * LC * BB + rowIdx];
                const float inv = 1.f / s;
                float4 acc = make_float4(0.f, 0.f, 0.f, 0.f);
                #pragma unroll
                for (int ks = 0; ks < KS; ks++) {
                    const size_t zz = (size_t)(h * KS + ks);
                    const __half2* p = (const __half2*)(g_part + (zz * N4 + i) * 4);
                    const float2 f0 = __half22float2(p[0]);
                    const float2 f1 = __half22float2(p[1]);
                    acc.x += f0.x; acc.y += f0.y; acc.z += f1.x; acc.w += f1.y;
                }
                r.x += acc.x * inv;
                r.y += acc.y * inv;
                r.z += acc.z * inv;
                r.w += acc.w * inv;
            }
            ((float4*)outp)[i] = r;
        }
    }
}

// ---------------------------------------------------------------------------
extern "C" void kernel_launch(void* const* d_in, const int* in_sizes, int n_in,
                              void* d_out, int out_size) {
    const int*   conv = (const int*)d_in[0];
    const int*   kb   = (const int*)d_in[1];
    const float* Ctab = (const float*)d_in[2];
    const float* Ktab = (const float*)d_in[3];
    float* out = (float*)d_out;

    const int smem_bytes = 3 * TK * KF_PITCH * 2;        // 52224
    cudaFuncSetAttribute(attn_kernel,
                         cudaFuncAttributeMaxDynamicSharedMemorySize, smem_bytes);

    const int n_rows = HOPS * BB * (LC + LK);            // 36864
    embed_kernel<<<n_rows / 4, 128>>>(conv, kb, Ctab, Ktab);
    attn_kernel<<<dim3(LC / TQ, BB, HOPS * KS), 128, smem_bytes>>>(out);
}